// round 4
// baseline (speedup 1.0000x reference)
#include <cuda_runtime.h>
#include <cstdint>

#define N_NODES 100000
#define N_EDGES 1600000
#define CH 64
#define EDIM 16
#define HID 32
#define NB_SCAN ((N_NODES + 1023) / 1024)   // 98

// Scratch (static device globals — allocation-free)
__device__ float g_xw[N_NODES * CH];              // x @ W
__device__ float g_alpha[N_EDGES];                // edge gate
__device__ float g_deg[N_NODES];                  // degree -> dis
__device__ int   g_cnt[N_NODES];
__device__ int   g_incl[N_NODES];
__device__ int   g_bsum[NB_SCAN];
__device__ int   g_boff[NB_SCAN];
__device__ int   g_rowptr[N_NODES];
__device__ int   g_wptr[N_NODES];
__device__ unsigned long long g_epack[N_EDGES];   // (norm<<32 | row) per CSR slot
__device__ int   g_is64;

// ---- packed f32x2 helpers ------------------------------------------------
__device__ __forceinline__ unsigned long long pk(float lo, float hi) {
    unsigned long long r;
    asm("mov.b64 %0,{%1,%2};" : "=l"(r) : "f"(lo), "f"(hi));
    return r;
}
__device__ __forceinline__ void upk(unsigned long long v, float& lo, float& hi) {
    asm("mov.b64 {%0,%1},%2;" : "=f"(lo), "=f"(hi) : "l"(v));
}
#define FMA2(d, a, b, c) \
    asm("fma.rn.f32x2 %0,%1,%2,%3;" : "=l"(d) : "l"(a), "l"(b), "l"(c))

// ---------------------------------------------------------------------------
// dtype detection for edge_index (JAX may silently downcast int64 -> int32)
// ---------------------------------------------------------------------------
__global__ void k_detect(const long long* __restrict__ ei64) {
    if (threadIdx.x == 0) {
        int ok = 1;
        #pragma unroll 1
        for (int i = 0; i < 64; ++i) {
            long long v = ei64[i];
            if (v < 0 || v >= N_NODES) { ok = 0; break; }
        }
        g_is64 = ok;
    }
}
__device__ __forceinline__ int edge_row(const void* ei, int e) {
    if (g_is64) return (int)((const long long*)ei)[e];
    return ((const int*)ei)[e];
}
__device__ __forceinline__ int edge_col(const void* ei, int e) {
    if (g_is64) return (int)((const long long*)ei)[(size_t)N_EDGES + e];
    return ((const int*)ei)[(size_t)N_EDGES + e];
}

// ---------------------------------------------------------------------------
__global__ void k_init() {
    int i = blockIdx.x * blockDim.x + threadIdx.x;
    if (i < N_NODES) { g_deg[i] = 0.0f; g_cnt[i] = 0; }
}

// ---------------------------------------------------------------------------
// 1) xw = x @ W
// ---------------------------------------------------------------------------
__global__ void k_xw(const float* __restrict__ x, const float* __restrict__ W) {
    __shared__ float Ws[CH * CH];
    for (int i = threadIdx.x; i < CH * CH; i += blockDim.x) Ws[i] = W[i];
    __syncthreads();
    const int c  = threadIdx.x & 63;
    const int ln = threadIdx.x >> 6;
    const int base = blockIdx.x * 64;
    for (int it = 0; it < 16; ++it) {
        int n = base + it * 4 + ln;
        if (n < N_NODES) {
            const float* xr = x + (size_t)n * CH;
            float acc = 0.0f;
            #pragma unroll
            for (int k = 0; k < CH; ++k) acc = fmaf(xr[k], Ws[k * CH + c], acc);
            g_xw[(size_t)n * CH + c] = acc;
        }
    }
}

// ---------------------------------------------------------------------------
// 2) edge MLP gate: 2 edges/thread, packed f32x2 math, duplicated weights
// ---------------------------------------------------------------------------
__global__ void k_edge(const float* __restrict__ ea,
                       const void* __restrict__ ei,
                       const float* __restrict__ W1, const float* __restrict__ b1,
                       const float* __restrict__ W2, const float* __restrict__ b2) {
    __shared__ __align__(16) float2 sW1d[HID * EDIM];  // [j][k] dup {w,w}
    __shared__ __align__(8)  float2 sb1d[HID];
    __shared__ __align__(8)  float2 sW2d[HID];
    __shared__ float sb2;
    for (int i = threadIdx.x; i < HID * EDIM; i += blockDim.x) {
        int j = i >> 4, k = i & 15;
        float w = W1[k * HID + j];
        sW1d[i] = make_float2(w, w);
    }
    if (threadIdx.x < HID) {
        float bb = b1[threadIdx.x]; sb1d[threadIdx.x] = make_float2(bb, bb);
        float ww = W2[threadIdx.x]; sW2d[threadIdx.x] = make_float2(ww, ww);
    }
    if (threadIdx.x == 0) sb2 = b2[0];
    __syncthreads();

    int t = blockIdx.x * blockDim.x + threadIdx.x;
    int e0 = 2 * t;
    if (e0 >= N_EDGES) return;      // N_EDGES is even -> e1 = e0+1 always valid

    // load + pack both edges' features
    unsigned long long ap[EDIM];
    {
        const float4* p0 = (const float4*)(ea + (size_t)e0 * EDIM);
        const float4* p1 = (const float4*)(ea + (size_t)(e0 + 1) * EDIM);
        #pragma unroll
        for (int i = 0; i < 4; ++i) {
            float4 a = p0[i], b = p1[i];
            ap[4*i+0] = pk(a.x, b.x);
            ap[4*i+1] = pk(a.y, b.y);
            ap[4*i+2] = pk(a.z, b.z);
            ap[4*i+3] = pk(a.w, b.w);
        }
    }

    unsigned long long acc = pk(sb2, sb2);
    #pragma unroll
    for (int j = 0; j < HID; ++j) {
        const ulonglong2* wr = (const ulonglong2*)(sW1d + j * EDIM);
        unsigned long long h = *(const unsigned long long*)&sb1d[j];
        #pragma unroll
        for (int q = 0; q < 8; ++q) {
            ulonglong2 w = wr[q];      // dup weights for k=2q, 2q+1
            FMA2(h, ap[2*q],   w.x, h);
            FMA2(h, ap[2*q+1], w.y, h);
        }
        float h0, h1; upk(h, h0, h1);
        float s0 = __fdividef(h0, 1.0f + __expf(-h0));   // silu
        float s1 = __fdividef(h1, 1.0f + __expf(-h1));
        unsigned long long s = pk(s0, s1);
        unsigned long long w2 = *(const unsigned long long*)&sW2d[j];
        FMA2(acc, s, w2, acc);
    }
    float a0, a1; upk(acc, a0, a1);
    float alpha0 = __fdividef(1.0f, 1.0f + __expf(-a0));
    float alpha1 = __fdividef(1.0f, 1.0f + __expf(-a1));
    ((float2*)g_alpha)[t] = make_float2(alpha0, alpha1);

    int col0 = edge_col(ei, e0);
    int col1 = edge_col(ei, e0 + 1);
    atomicAdd(&g_deg[col0], alpha0);
    atomicAdd(&g_deg[col1], alpha1);
    atomicAdd(&g_cnt[col0], 1);
    atomicAdd(&g_cnt[col1], 1);
}

// ---------------------------------------------------------------------------
// 3a/3b/3c) scan of cnt -> rowptr; dis = rsqrt(deg)
// ---------------------------------------------------------------------------
__global__ void k_scan1() {
    int i = blockIdx.x * 1024 + threadIdx.x;
    int v = (i < N_NODES) ? g_cnt[i] : 0;
    int lane = threadIdx.x & 31, wid = threadIdx.x >> 5;
    int s = v;
    #pragma unroll
    for (int o = 1; o < 32; o <<= 1) {
        int t = __shfl_up_sync(0xffffffffu, s, o);
        if (lane >= o) s += t;
    }
    __shared__ int wsum[32];
    if (lane == 31) wsum[wid] = s;
    __syncthreads();
    if (wid == 0) {
        int t = wsum[lane];
        #pragma unroll
        for (int o = 1; o < 32; o <<= 1) {
            int u = __shfl_up_sync(0xffffffffu, t, o);
            if (lane >= o) t += u;
        }
        wsum[lane] = t;
    }
    __syncthreads();
    int incl = s + (wid > 0 ? wsum[wid - 1] : 0);
    if (i < N_NODES) g_incl[i] = incl;
    if (threadIdx.x == 1023) g_bsum[blockIdx.x] = incl;
}

__global__ void k_scan2() {
    if (threadIdx.x == 0) {
        int run = 0;
        #pragma unroll 1
        for (int b = 0; b < NB_SCAN; ++b) { g_boff[b] = run; run += g_bsum[b]; }
    }
}

__global__ void k_final() {
    int i = blockIdx.x * blockDim.x + threadIdx.x;
    if (i < N_NODES) {
        int excl = g_incl[i] - g_cnt[i] + g_boff[i >> 10];
        g_rowptr[i] = excl;
        g_wptr[i] = excl;
        float d = g_deg[i];
        g_deg[i] = (d > 0.0f) ? rsqrtf(d) : 0.0f;
    }
}

// ---------------------------------------------------------------------------
// 4) placement: drop packed (row, norm) into col's CSR slot (one STG.64)
// ---------------------------------------------------------------------------
__global__ void k_place(const void* __restrict__ ei) {
    int e = blockIdx.x * blockDim.x + threadIdx.x;
    if (e >= N_EDGES) return;
    int row = edge_row(ei, e);
    int col = edge_col(ei, e);
    float norm = g_deg[row] * g_alpha[e] * g_deg[col];
    int pos = atomicAdd(&g_wptr[col], 1);
    unsigned long long v = (unsigned)row |
                           ((unsigned long long)__float_as_uint(norm) << 32);
    g_epack[pos] = v;
}

// ---------------------------------------------------------------------------
// 5) gather + bias + LayerNorm + SiLU + residual.  One warp per node.
//    Edges staged in smem; inner loop unrolled x4 with 4 accumulator pairs.
// ---------------------------------------------------------------------------
__global__ void k_gather_ln(const float* __restrict__ x, const float* __restrict__ b,
                            const float* __restrict__ gamma, const float* __restrict__ beta,
                            float* __restrict__ out) {
    __shared__ unsigned long long stage[8][32];
    int wip  = threadIdx.x >> 5;
    int lane = threadIdx.x & 31;
    int node = (blockIdx.x * blockDim.x + threadIdx.x) >> 5;
    if (node >= N_NODES) return;

    int start = g_rowptr[node];
    int cnt   = g_cnt[node];

    float a0x = 0.f, a0y = 0.f, a1x = 0.f, a1y = 0.f;
    float a2x = 0.f, a2y = 0.f, a3x = 0.f, a3y = 0.f;

    for (int base = 0; base < cnt; base += 32) {
        int m = cnt - base; if (m > 32) m = 32;
        unsigned long long p = 0ull;            // row=0, norm=0 padding
        if (lane < m) p = g_epack[start + base + lane];
        stage[wip][lane] = p;
        __syncwarp();
        int m4 = (m + 3) & ~3;
        #pragma unroll 1
        for (int j = 0; j < m4; j += 4) {
            unsigned long long p0 = stage[wip][j + 0];
            unsigned long long p1 = stage[wip][j + 1];
            unsigned long long p2 = stage[wip][j + 2];
            unsigned long long p3 = stage[wip][j + 3];
            int   r0 = (int)(unsigned)p0;  float w0 = __uint_as_float((unsigned)(p0 >> 32));
            int   r1 = (int)(unsigned)p1;  float w1 = __uint_as_float((unsigned)(p1 >> 32));
            int   r2 = (int)(unsigned)p2;  float w2 = __uint_as_float((unsigned)(p2 >> 32));
            int   r3 = (int)(unsigned)p3;  float w3 = __uint_as_float((unsigned)(p3 >> 32));
            float2 v0 = ((const float2*)(g_xw + (size_t)r0 * CH))[lane];
            float2 v1 = ((const float2*)(g_xw + (size_t)r1 * CH))[lane];
            float2 v2 = ((const float2*)(g_xw + (size_t)r2 * CH))[lane];
            float2 v3 = ((const float2*)(g_xw + (size_t)r3 * CH))[lane];
            a0x = fmaf(v0.x, w0, a0x); a0y = fmaf(v0.y, w0, a0y);
            a1x = fmaf(v1.x, w1, a1x); a1y = fmaf(v1.y, w1, a1y);
            a2x = fmaf(v2.x, w2, a2x); a2y = fmaf(v2.y, w2, a2y);
            a3x = fmaf(v3.x, w3, a3x); a3y = fmaf(v3.y, w3, a3y);
        }
        __syncwarp();
    }

    float2 bb = ((const float2*)b)[lane];
    float h0 = (a0x + a1x) + (a2x + a3x) + bb.x;
    float h1 = (a0y + a1y) + (a2y + a3y) + bb.y;

    // LayerNorm over 64 channels
    float s = h0 + h1;
    #pragma unroll
    for (int o = 16; o > 0; o >>= 1) s += __shfl_xor_sync(0xffffffffu, s, o);
    float mu = s * (1.0f / 64.0f);
    float d0 = h0 - mu, d1 = h1 - mu;
    float vs = d0 * d0 + d1 * d1;
    #pragma unroll
    for (int o = 16; o > 0; o >>= 1) vs += __shfl_xor_sync(0xffffffffu, vs, o);
    float inv = rsqrtf(vs * (1.0f / 64.0f) + 1e-5f);

    float2 gg = ((const float2*)gamma)[lane];
    float2 be = ((const float2*)beta)[lane];
    float y0 = fmaf(d0 * inv, gg.x, be.x);
    float y1 = fmaf(d1 * inv, gg.y, be.y);
    y0 = __fdividef(y0, 1.0f + __expf(-y0));
    y1 = __fdividef(y1, 1.0f + __expf(-y1));

    float2 xv = ((const float2*)(x + (size_t)node * CH))[lane];
    ((float2*)(out + (size_t)node * CH))[lane] = make_float2(y0 + xv.x, y1 + xv.y);
}

// ---------------------------------------------------------------------------
extern "C" void kernel_launch(void* const* d_in, const int* in_sizes, int n_in,
                              void* d_out, int out_size) {
    const float* x     = (const float*)d_in[0];
    const void*  ei    = d_in[1];
    const float* ea    = (const float*)d_in[2];
    const float* W     = (const float*)d_in[3];
    const float* b     = (const float*)d_in[4];
    const float* W1    = (const float*)d_in[5];
    const float* b1    = (const float*)d_in[6];
    const float* W2    = (const float*)d_in[7];
    const float* b2    = (const float*)d_in[8];
    const float* gamma = (const float*)d_in[9];
    const float* beta  = (const float*)d_in[10];
    float* out = (float*)d_out;

    k_detect<<<1, 32>>>((const long long*)ei);
    k_init<<<(N_NODES + 255) / 256, 256>>>();
    k_xw<<<(N_NODES + 63) / 64, 256>>>(x, W);
    k_edge<<<(N_EDGES / 2 + 255) / 256, 256>>>(ea, ei, W1, b1, W2, b2);
    k_scan1<<<NB_SCAN, 1024>>>();
    k_scan2<<<1, 32>>>();
    k_final<<<(N_NODES + 255) / 256, 256>>>();
    k_place<<<(N_EDGES + 255) / 256, 256>>>(ei);
    k_gather_ln<<<(N_NODES + 7) / 8, 256>>>(x, b, gamma, beta, out);
}

// round 5
// speedup vs baseline: 1.1106x; 1.1106x over previous
#include <cuda_runtime.h>
#include <cstdint>

#define N_NODES 100000
#define N_EDGES 1600000
#define CH 64
#define EDIM 16
#define HID 32
#define NB_SCAN ((N_NODES + 1023) / 1024)   // 98

// Scratch (static device globals — allocation-free)
__device__ float g_xw[N_NODES * CH];              // x @ W
__device__ float g_alpha[N_EDGES];                // edge gate
__device__ float g_deg[N_NODES];                  // degree -> dis
__device__ int   g_cnt[N_NODES];
__device__ int   g_incl[N_NODES];
__device__ int   g_bsum[NB_SCAN];
__device__ int   g_boff[NB_SCAN];
__device__ int   g_rowptr[N_NODES];
__device__ int   g_wptr[N_NODES];
__device__ unsigned long long g_epack[N_EDGES];   // (norm<<32 | row) per CSR slot
__device__ int   g_is64;

// ---------------------------------------------------------------------------
// dtype detection (thread 0 of block 0) + zero deg/cnt
// ---------------------------------------------------------------------------
__global__ void k_detect_init(const long long* __restrict__ ei64) {
    int i = blockIdx.x * blockDim.x + threadIdx.x;
    if (i == 0) {
        int ok = 1;
        #pragma unroll 1
        for (int k = 0; k < 64; ++k) {
            long long v = ei64[k];
            if (v < 0 || v >= N_NODES) { ok = 0; break; }
        }
        g_is64 = ok;
    }
    if (i < N_NODES) { g_deg[i] = 0.0f; g_cnt[i] = 0; }
}

__device__ __forceinline__ int edge_row(const void* ei, int e) {
    if (g_is64) return (int)((const long long*)ei)[e];
    return ((const int*)ei)[e];
}
__device__ __forceinline__ int edge_col(const void* ei, int e) {
    if (g_is64) return (int)((const long long*)ei)[(size_t)N_EDGES + e];
    return ((const int*)ei)[(size_t)N_EDGES + e];
}

// ---------------------------------------------------------------------------
// 1) xw = x @ W   (independent of the edge chain -> runs on side stream)
// ---------------------------------------------------------------------------
__global__ void k_xw(const float* __restrict__ x, const float* __restrict__ W) {
    __shared__ float Ws[CH * CH];
    for (int i = threadIdx.x; i < CH * CH; i += blockDim.x) Ws[i] = W[i];
    __syncthreads();
    const int c  = threadIdx.x & 63;
    const int ln = threadIdx.x >> 6;
    const int base = blockIdx.x * 64;
    for (int it = 0; it < 16; ++it) {
        int n = base + it * 4 + ln;
        if (n < N_NODES) {
            const float* xr = x + (size_t)n * CH;
            float acc = 0.0f;
            #pragma unroll
            for (int k = 0; k < CH; ++k) acc = fmaf(xr[k], Ws[k * CH + c], acc);
            g_xw[(size_t)n * CH + c] = acc;
        }
    }
}

// ---------------------------------------------------------------------------
// 2) edge MLP gate + degree + count.  W1 transposed in smem -> LDS.128.
//    (R3-proven version: 46 regs, scalar FFMA)
// ---------------------------------------------------------------------------
__global__ void k_edge(const float* __restrict__ ea,
                       const void* __restrict__ ei,
                       const float* __restrict__ W1, const float* __restrict__ b1,
                       const float* __restrict__ W2, const float* __restrict__ b2) {
    __shared__ __align__(16) float sW1t[HID * EDIM];   // [j][k] transposed
    __shared__ float sb1[HID];
    __shared__ float sW2[HID];
    __shared__ float sb2;
    for (int i = threadIdx.x; i < HID * EDIM; i += blockDim.x) {
        int j = i >> 4, k = i & 15;
        sW1t[i] = W1[k * HID + j];
    }
    if (threadIdx.x < HID) { sb1[threadIdx.x] = b1[threadIdx.x]; sW2[threadIdx.x] = W2[threadIdx.x]; }
    if (threadIdx.x == 0) sb2 = b2[0];
    __syncthreads();

    int e = blockIdx.x * blockDim.x + threadIdx.x;
    if (e >= N_EDGES) return;

    float4 a0, a1, a2, a3;
    {
        const float4* p = (const float4*)(ea + (size_t)e * EDIM);
        a0 = p[0]; a1 = p[1]; a2 = p[2]; a3 = p[3];
    }

    const float4* Wt = (const float4*)sW1t;
    float acc = sb2;
    #pragma unroll
    for (int j = 0; j < HID; ++j) {
        float4 w0 = Wt[j * 4 + 0], w1 = Wt[j * 4 + 1], w2 = Wt[j * 4 + 2], w3 = Wt[j * 4 + 3];
        float h = sb1[j];
        h = fmaf(a0.x, w0.x, h); h = fmaf(a0.y, w0.y, h); h = fmaf(a0.z, w0.z, h); h = fmaf(a0.w, w0.w, h);
        h = fmaf(a1.x, w1.x, h); h = fmaf(a1.y, w1.y, h); h = fmaf(a1.z, w1.z, h); h = fmaf(a1.w, w1.w, h);
        h = fmaf(a2.x, w2.x, h); h = fmaf(a2.y, w2.y, h); h = fmaf(a2.z, w2.z, h); h = fmaf(a2.w, w2.w, h);
        h = fmaf(a3.x, w3.x, h); h = fmaf(a3.y, w3.y, h); h = fmaf(a3.z, w3.z, h); h = fmaf(a3.w, w3.w, h);
        float s = __fdividef(h, 1.0f + __expf(-h));    // silu
        acc = fmaf(s, sW2[j], acc);
    }
    float alpha = __fdividef(1.0f, 1.0f + __expf(-acc)); // sigmoid
    g_alpha[e] = alpha;

    int col = edge_col(ei, e);
    atomicAdd(&g_deg[col], alpha);
    atomicAdd(&g_cnt[col], 1);
}

// ---------------------------------------------------------------------------
// 3a/3b/3c) scan of cnt -> rowptr; dis = rsqrt(deg)
// ---------------------------------------------------------------------------
__global__ void k_scan1() {
    int i = blockIdx.x * 1024 + threadIdx.x;
    int v = (i < N_NODES) ? g_cnt[i] : 0;
    int lane = threadIdx.x & 31, wid = threadIdx.x >> 5;
    int s = v;
    #pragma unroll
    for (int o = 1; o < 32; o <<= 1) {
        int t = __shfl_up_sync(0xffffffffu, s, o);
        if (lane >= o) s += t;
    }
    __shared__ int wsum[32];
    if (lane == 31) wsum[wid] = s;
    __syncthreads();
    if (wid == 0) {
        int t = wsum[lane];
        #pragma unroll
        for (int o = 1; o < 32; o <<= 1) {
            int u = __shfl_up_sync(0xffffffffu, t, o);
            if (lane >= o) t += u;
        }
        wsum[lane] = t;
    }
    __syncthreads();
    int incl = s + (wid > 0 ? wsum[wid - 1] : 0);
    if (i < N_NODES) g_incl[i] = incl;
    if (threadIdx.x == 1023) g_bsum[blockIdx.x] = incl;
}

__global__ void k_scan2() {
    if (threadIdx.x == 0) {
        int run = 0;
        #pragma unroll 1
        for (int b = 0; b < NB_SCAN; ++b) { g_boff[b] = run; run += g_bsum[b]; }
    }
}

__global__ void k_final() {
    int i = blockIdx.x * blockDim.x + threadIdx.x;
    if (i < N_NODES) {
        int excl = g_incl[i] - g_cnt[i] + g_boff[i >> 10];
        g_rowptr[i] = excl;
        g_wptr[i] = excl;
        float d = g_deg[i];
        g_deg[i] = (d > 0.0f) ? rsqrtf(d) : 0.0f;
    }
}

// ---------------------------------------------------------------------------
// 4) placement: drop packed (row, norm) into col's CSR slot (one STG.64)
// ---------------------------------------------------------------------------
__global__ void k_place(const void* __restrict__ ei) {
    int e = blockIdx.x * blockDim.x + threadIdx.x;
    if (e >= N_EDGES) return;
    int row = edge_row(ei, e);
    int col = edge_col(ei, e);
    float norm = g_deg[row] * g_alpha[e] * g_deg[col];
    int pos = atomicAdd(&g_wptr[col], 1);
    unsigned long long v = (unsigned)row |
                           ((unsigned long long)__float_as_uint(norm) << 32);
    g_epack[pos] = v;
}

// ---------------------------------------------------------------------------
// 5) gather + bias + LayerNorm + SiLU + residual.  One warp per node.
//    Edges staged in smem; inner loop unrolled x4 with 4 accumulator pairs.
// ---------------------------------------------------------------------------
__global__ void k_gather_ln(const float* __restrict__ x, const float* __restrict__ b,
                            const float* __restrict__ gamma, const float* __restrict__ beta,
                            float* __restrict__ out) {
    __shared__ unsigned long long stage[8][32];
    int wip  = threadIdx.x >> 5;
    int lane = threadIdx.x & 31;
    int node = (blockIdx.x * blockDim.x + threadIdx.x) >> 5;
    if (node >= N_NODES) return;

    int start = g_rowptr[node];
    int cnt   = g_cnt[node];

    float a0x = 0.f, a0y = 0.f, a1x = 0.f, a1y = 0.f;
    float a2x = 0.f, a2y = 0.f, a3x = 0.f, a3y = 0.f;

    for (int base = 0; base < cnt; base += 32) {
        int m = cnt - base; if (m > 32) m = 32;
        unsigned long long p = 0ull;            // row=0, norm=0 padding
        if (lane < m) p = g_epack[start + base + lane];
        stage[wip][lane] = p;
        __syncwarp();
        int m4 = (m + 3) & ~3;
        #pragma unroll 1
        for (int j = 0; j < m4; j += 4) {
            unsigned long long p0 = stage[wip][j + 0];
            unsigned long long p1 = stage[wip][j + 1];
            unsigned long long p2 = stage[wip][j + 2];
            unsigned long long p3 = stage[wip][j + 3];
            int   r0 = (int)(unsigned)p0;  float w0 = __uint_as_float((unsigned)(p0 >> 32));
            int   r1 = (int)(unsigned)p1;  float w1 = __uint_as_float((unsigned)(p1 >> 32));
            int   r2 = (int)(unsigned)p2;  float w2 = __uint_as_float((unsigned)(p2 >> 32));
            int   r3 = (int)(unsigned)p3;  float w3 = __uint_as_float((unsigned)(p3 >> 32));
            float2 v0 = ((const float2*)(g_xw + (size_t)r0 * CH))[lane];
            float2 v1 = ((const float2*)(g_xw + (size_t)r1 * CH))[lane];
            float2 v2 = ((const float2*)(g_xw + (size_t)r2 * CH))[lane];
            float2 v3 = ((const float2*)(g_xw + (size_t)r3 * CH))[lane];
            a0x = fmaf(v0.x, w0, a0x); a0y = fmaf(v0.y, w0, a0y);
            a1x = fmaf(v1.x, w1, a1x); a1y = fmaf(v1.y, w1, a1y);
            a2x = fmaf(v2.x, w2, a2x); a2y = fmaf(v2.y, w2, a2y);
            a3x = fmaf(v3.x, w3, a3x); a3y = fmaf(v3.y, w3, a3y);
        }
        __syncwarp();
    }

    float2 bb = ((const float2*)b)[lane];
    float h0 = (a0x + a1x) + (a2x + a3x) + bb.x;
    float h1 = (a0y + a1y) + (a2y + a3y) + bb.y;

    // LayerNorm over 64 channels
    float s = h0 + h1;
    #pragma unroll
    for (int o = 16; o > 0; o >>= 1) s += __shfl_xor_sync(0xffffffffu, s, o);
    float mu = s * (1.0f / 64.0f);
    float d0 = h0 - mu, d1 = h1 - mu;
    float vs = d0 * d0 + d1 * d1;
    #pragma unroll
    for (int o = 16; o > 0; o >>= 1) vs += __shfl_xor_sync(0xffffffffu, vs, o);
    float inv = rsqrtf(vs * (1.0f / 64.0f) + 1e-5f);

    float2 gg = ((const float2*)gamma)[lane];
    float2 be = ((const float2*)beta)[lane];
    float y0 = fmaf(d0 * inv, gg.x, be.x);
    float y1 = fmaf(d1 * inv, gg.y, be.y);
    y0 = __fdividef(y0, 1.0f + __expf(-y0));
    y1 = __fdividef(y1, 1.0f + __expf(-y1));

    float2 xv = ((const float2*)(x + (size_t)node * CH))[lane];
    ((float2*)(out + (size_t)node * CH))[lane] = make_float2(y0 + xv.x, y1 + xv.y);
}

// ---------------------------------------------------------------------------
extern "C" void kernel_launch(void* const* d_in, const int* in_sizes, int n_in,
                              void* d_out, int out_size) {
    const float* x     = (const float*)d_in[0];
    const void*  ei    = d_in[1];
    const float* ea    = (const float*)d_in[2];
    const float* W     = (const float*)d_in[3];
    const float* b     = (const float*)d_in[4];
    const float* W1    = (const float*)d_in[5];
    const float* b1    = (const float*)d_in[6];
    const float* W2    = (const float*)d_in[7];
    const float* b2    = (const float*)d_in[8];
    const float* gamma = (const float*)d_in[9];
    const float* beta  = (const float*)d_in[10];
    float* out = (float*)d_out;

    // Static side-stream + events (created once, on the uncaptured
    // correctness call; reused identically on the capture call).
    static cudaStream_t s_side = nullptr;
    static cudaEvent_t  s_evFork = nullptr, s_evJoin = nullptr;
    if (!s_side) {
        cudaStreamCreateWithFlags(&s_side, cudaStreamNonBlocking);
        cudaEventCreateWithFlags(&s_evFork, cudaEventDisableTiming);
        cudaEventCreateWithFlags(&s_evJoin, cudaEventDisableTiming);
    }

    // fork: xw on side stream, hidden under the edge chain
    cudaEventRecord(s_evFork, 0);
    cudaStreamWaitEvent(s_side, s_evFork, 0);
    k_xw<<<(N_NODES + 63) / 64, 256, 0, s_side>>>(x, W);
    cudaEventRecord(s_evJoin, s_side);

    // main chain
    k_detect_init<<<(N_NODES + 255) / 256, 256>>>((const long long*)ei);
    k_edge<<<(N_EDGES + 255) / 256, 256>>>(ea, ei, W1, b1, W2, b2);
    k_scan1<<<NB_SCAN, 1024>>>();
    k_scan2<<<1, 32>>>();
    k_final<<<(N_NODES + 255) / 256, 256>>>();
    k_place<<<(N_EDGES + 255) / 256, 256>>>(ei);

    // join: gather needs g_xw
    cudaStreamWaitEvent(0, s_evJoin, 0);
    k_gather_ln<<<(N_NODES + 7) / 8, 256>>>(x, b, gamma, beta, out);
}

// round 6
// speedup vs baseline: 1.1251x; 1.0131x over previous
#include <cuda_runtime.h>
#include <cstdint>

#define N_NODES 100000
#define N_EDGES 1600000
#define CH 64
#define EDIM 16
#define HID 32
#define NB_SCAN ((N_NODES + 1023) / 1024)   // 98

// Scratch (static device globals — allocation-free)
__device__ float g_xw[N_NODES * CH];              // x @ W
__device__ float g_alpha[N_EDGES];                // edge gate
__device__ float g_deg[N_NODES];                  // degree -> dis
__device__ int   g_cnt[N_NODES];
__device__ int   g_incl[N_NODES];
__device__ int   g_bsum[NB_SCAN];
__device__ int   g_boff[NB_SCAN];
__device__ int   g_rowptr[N_NODES];
__device__ int   g_wptr[N_NODES];
__device__ unsigned long long g_epack[N_EDGES];   // (norm<<32 | row) per CSR slot
__device__ int   g_is64;

// ---------------------------------------------------------------------------
// dtype detection (thread 0 of block 0) + zero deg/cnt
// ---------------------------------------------------------------------------
__global__ void k_detect_init(const long long* __restrict__ ei64) {
    int i = blockIdx.x * blockDim.x + threadIdx.x;
    if (i == 0) {
        int ok = 1;
        #pragma unroll 1
        for (int k = 0; k < 64; ++k) {
            long long v = ei64[k];
            if (v < 0 || v >= N_NODES) { ok = 0; break; }
        }
        g_is64 = ok;
    }
    if (i < N_NODES) { g_deg[i] = 0.0f; g_cnt[i] = 0; }
}

__device__ __forceinline__ int edge_row(const void* ei, int e) {
    if (g_is64) return (int)((const long long*)ei)[e];
    return ((const int*)ei)[e];
}
__device__ __forceinline__ int edge_col(const void* ei, int e) {
    if (g_is64) return (int)((const long long*)ei)[(size_t)N_EDGES + e];
    return ((const int*)ei)[(size_t)N_EDGES + e];
}

// ---------------------------------------------------------------------------
// 1) xw = x @ W   (independent of the edge chain -> runs on side stream)
// ---------------------------------------------------------------------------
__global__ void k_xw(const float* __restrict__ x, const float* __restrict__ W) {
    __shared__ float Ws[CH * CH];
    for (int i = threadIdx.x; i < CH * CH; i += blockDim.x) Ws[i] = W[i];
    __syncthreads();
    const int c  = threadIdx.x & 63;
    const int ln = threadIdx.x >> 6;
    const int base = blockIdx.x * 64;
    for (int it = 0; it < 16; ++it) {
        int n = base + it * 4 + ln;
        if (n < N_NODES) {
            const float* xr = x + (size_t)n * CH;
            float acc = 0.0f;
            #pragma unroll
            for (int k = 0; k < CH; ++k) acc = fmaf(xr[k], Ws[k * CH + c], acc);
            g_xw[(size_t)n * CH + c] = acc;
        }
    }
}

// ---------------------------------------------------------------------------
// 2) edge MLP gate + degree + count.  W1 transposed in smem -> LDS.128.
// ---------------------------------------------------------------------------
__global__ void k_edge(const float* __restrict__ ea,
                       const void* __restrict__ ei,
                       const float* __restrict__ W1, const float* __restrict__ b1,
                       const float* __restrict__ W2, const float* __restrict__ b2) {
    __shared__ __align__(16) float sW1t[HID * EDIM];   // [j][k] transposed
    __shared__ float sb1[HID];
    __shared__ float sW2[HID];
    __shared__ float sb2;
    for (int i = threadIdx.x; i < HID * EDIM; i += blockDim.x) {
        int j = i >> 4, k = i & 15;
        sW1t[i] = W1[k * HID + j];
    }
    if (threadIdx.x < HID) { sb1[threadIdx.x] = b1[threadIdx.x]; sW2[threadIdx.x] = W2[threadIdx.x]; }
    if (threadIdx.x == 0) sb2 = b2[0];
    __syncthreads();

    int e = blockIdx.x * blockDim.x + threadIdx.x;
    if (e >= N_EDGES) return;

    float4 a0, a1, a2, a3;
    {
        const float4* p = (const float4*)(ea + (size_t)e * EDIM);
        a0 = p[0]; a1 = p[1]; a2 = p[2]; a3 = p[3];
    }

    const float4* Wt = (const float4*)sW1t;
    float acc = sb2;
    #pragma unroll
    for (int j = 0; j < HID; ++j) {
        float4 w0 = Wt[j * 4 + 0], w1 = Wt[j * 4 + 1], w2 = Wt[j * 4 + 2], w3 = Wt[j * 4 + 3];
        float h = sb1[j];
        h = fmaf(a0.x, w0.x, h); h = fmaf(a0.y, w0.y, h); h = fmaf(a0.z, w0.z, h); h = fmaf(a0.w, w0.w, h);
        h = fmaf(a1.x, w1.x, h); h = fmaf(a1.y, w1.y, h); h = fmaf(a1.z, w1.z, h); h = fmaf(a1.w, w1.w, h);
        h = fmaf(a2.x, w2.x, h); h = fmaf(a2.y, w2.y, h); h = fmaf(a2.z, w2.z, h); h = fmaf(a2.w, w2.w, h);
        h = fmaf(a3.x, w3.x, h); h = fmaf(a3.y, w3.y, h); h = fmaf(a3.z, w3.z, h); h = fmaf(a3.w, w3.w, h);
        float s = __fdividef(h, 1.0f + __expf(-h));    // silu
        acc = fmaf(s, sW2[j], acc);
    }
    float alpha = __fdividef(1.0f, 1.0f + __expf(-acc)); // sigmoid
    g_alpha[e] = alpha;

    int col = edge_col(ei, e);
    atomicAdd(&g_deg[col], alpha);
    atomicAdd(&g_cnt[col], 1);
}

// ---------------------------------------------------------------------------
// 3a/3b/3c) scan of cnt -> rowptr; dis = rsqrt(deg)
// ---------------------------------------------------------------------------
__global__ void k_scan1() {
    int i = blockIdx.x * 1024 + threadIdx.x;
    int v = (i < N_NODES) ? g_cnt[i] : 0;
    int lane = threadIdx.x & 31, wid = threadIdx.x >> 5;
    int s = v;
    #pragma unroll
    for (int o = 1; o < 32; o <<= 1) {
        int t = __shfl_up_sync(0xffffffffu, s, o);
        if (lane >= o) s += t;
    }
    __shared__ int wsum[32];
    if (lane == 31) wsum[wid] = s;
    __syncthreads();
    if (wid == 0) {
        int t = wsum[lane];
        #pragma unroll
        for (int o = 1; o < 32; o <<= 1) {
            int u = __shfl_up_sync(0xffffffffu, t, o);
            if (lane >= o) t += u;
        }
        wsum[lane] = t;
    }
    __syncthreads();
    int incl = s + (wid > 0 ? wsum[wid - 1] : 0);
    if (i < N_NODES) g_incl[i] = incl;
    if (threadIdx.x == 1023) g_bsum[blockIdx.x] = incl;
}

__global__ void k_scan2() {
    if (threadIdx.x == 0) {
        int run = 0;
        #pragma unroll 1
        for (int b = 0; b < NB_SCAN; ++b) { g_boff[b] = run; run += g_bsum[b]; }
    }
}

__global__ void k_final() {
    int i = blockIdx.x * blockDim.x + threadIdx.x;
    if (i < N_NODES) {
        int excl = g_incl[i] - g_cnt[i] + g_boff[i >> 10];
        g_rowptr[i] = excl;
        g_wptr[i] = excl;
        float d = g_deg[i];
        g_deg[i] = (d > 0.0f) ? rsqrtf(d) : 0.0f;
    }
}

// ---------------------------------------------------------------------------
// 4) placement: drop packed (row, norm) into col's CSR slot (one STG.64)
// ---------------------------------------------------------------------------
__global__ void k_place(const void* __restrict__ ei) {
    int e = blockIdx.x * blockDim.x + threadIdx.x;
    if (e >= N_EDGES) return;
    int row, col;
    if (g_is64) {
        row = (int)((const long long*)ei)[e];
        col = (int)((const long long*)ei)[(size_t)N_EDGES + e];
    } else {
        row = ((const int*)ei)[e];
        col = ((const int*)ei)[(size_t)N_EDGES + e];
    }
    float norm = g_deg[row] * g_alpha[e] * g_deg[col];
    int pos = atomicAdd(&g_wptr[col], 1);
    unsigned long long v = (unsigned)row |
                           ((unsigned long long)__float_as_uint(norm) << 32);
    g_epack[pos] = v;
}

// ---------------------------------------------------------------------------
// 5) gather + bias + LayerNorm + SiLU + residual.  One warp per node.
//    8-wide unroll: 8 independent L2 gathers in flight before any FMA (MLP=8).
// ---------------------------------------------------------------------------
__global__ void k_gather_ln(const float* __restrict__ x, const float* __restrict__ b,
                            const float* __restrict__ gamma, const float* __restrict__ beta,
                            float* __restrict__ out) {
    __shared__ unsigned long long stage[8][40];   // 32 + 8 pad (zeros for tail)
    int wip  = threadIdx.x >> 5;
    int lane = threadIdx.x & 31;
    int node = (blockIdx.x * blockDim.x + threadIdx.x) >> 5;
    if (node >= N_NODES) return;

    // zero the pad slots once
    if (lane < 8) stage[wip][32 + lane] = 0ull;

    int start = g_rowptr[node];
    int cnt   = g_cnt[node];

    float ax[8], ay[8];
    #pragma unroll
    for (int i = 0; i < 8; ++i) { ax[i] = 0.f; ay[i] = 0.f; }

    for (int base = 0; base < cnt; base += 32) {
        int m = cnt - base; if (m > 32) m = 32;
        unsigned long long p = 0ull;            // row=0, norm=0 padding
        if (lane < m) p = g_epack[start + base + lane];
        stage[wip][lane] = p;
        __syncwarp();
        int m8 = (m + 7) & ~7;
        #pragma unroll 1
        for (int j = 0; j < m8; j += 8) {
            int   r[8]; float w[8];
            #pragma unroll
            for (int q = 0; q < 8; ++q) {
                unsigned long long pq = stage[wip][j + q];
                r[q] = (int)(unsigned)pq;
                w[q] = __uint_as_float((unsigned)(pq >> 32));
            }
            float2 v[8];
            #pragma unroll
            for (int q = 0; q < 8; ++q)
                v[q] = ((const float2*)(g_xw + (size_t)r[q] * CH))[lane];
            #pragma unroll
            for (int q = 0; q < 8; ++q) {
                ax[q] = fmaf(v[q].x, w[q], ax[q]);
                ay[q] = fmaf(v[q].y, w[q], ay[q]);
            }
        }
        __syncwarp();
    }

    float2 bb = ((const float2*)b)[lane];
    float h0 = ((ax[0] + ax[1]) + (ax[2] + ax[3])) + ((ax[4] + ax[5]) + (ax[6] + ax[7])) + bb.x;
    float h1 = ((ay[0] + ay[1]) + (ay[2] + ay[3])) + ((ay[4] + ay[5]) + (ay[6] + ay[7])) + bb.y;

    // LayerNorm over 64 channels
    float s = h0 + h1;
    #pragma unroll
    for (int o = 16; o > 0; o >>= 1) s += __shfl_xor_sync(0xffffffffu, s, o);
    float mu = s * (1.0f / 64.0f);
    float d0 = h0 - mu, d1 = h1 - mu;
    float vs = d0 * d0 + d1 * d1;
    #pragma unroll
    for (int o = 16; o > 0; o >>= 1) vs += __shfl_xor_sync(0xffffffffu, vs, o);
    float inv = rsqrtf(vs * (1.0f / 64.0f) + 1e-5f);

    float2 gg = ((const float2*)gamma)[lane];
    float2 be = ((const float2*)beta)[lane];
    float y0 = fmaf(d0 * inv, gg.x, be.x);
    float y1 = fmaf(d1 * inv, gg.y, be.y);
    y0 = __fdividef(y0, 1.0f + __expf(-y0));
    y1 = __fdividef(y1, 1.0f + __expf(-y1));

    float2 xv = ((const float2*)(x + (size_t)node * CH))[lane];
    ((float2*)(out + (size_t)node * CH))[lane] = make_float2(y0 + xv.x, y1 + xv.y);
}

// ---------------------------------------------------------------------------
extern "C" void kernel_launch(void* const* d_in, const int* in_sizes, int n_in,
                              void* d_out, int out_size) {
    const float* x     = (const float*)d_in[0];
    const void*  ei    = d_in[1];
    const float* ea    = (const float*)d_in[2];
    const float* W     = (const float*)d_in[3];
    const float* b     = (const float*)d_in[4];
    const float* W1    = (const float*)d_in[5];
    const float* b1    = (const float*)d_in[6];
    const float* W2    = (const float*)d_in[7];
    const float* b2    = (const float*)d_in[8];
    const float* gamma = (const float*)d_in[9];
    const float* beta  = (const float*)d_in[10];
    float* out = (float*)d_out;

    static cudaStream_t s_side = nullptr;
    static cudaEvent_t  s_evFork = nullptr, s_evJoin = nullptr;
    if (!s_side) {
        cudaStreamCreateWithFlags(&s_side, cudaStreamNonBlocking);
        cudaEventCreateWithFlags(&s_evFork, cudaEventDisableTiming);
        cudaEventCreateWithFlags(&s_evJoin, cudaEventDisableTiming);
    }

    // fork: xw on side stream, hidden under the edge chain
    cudaEventRecord(s_evFork, 0);
    cudaStreamWaitEvent(s_side, s_evFork, 0);
    k_xw<<<(N_NODES + 63) / 64, 256, 0, s_side>>>(x, W);
    cudaEventRecord(s_evJoin, s_side);

    // main chain
    k_detect_init<<<(N_NODES + 255) / 256, 256>>>((const long long*)ei);
    k_edge<<<(N_EDGES + 255) / 256, 256>>>(ea, ei, W1, b1, W2, b2);
    k_scan1<<<NB_SCAN, 1024>>>();
    k_scan2<<<1, 32>>>();
    k_final<<<(N_NODES + 255) / 256, 256>>>();
    k_place<<<(N_EDGES + 255) / 256, 256>>>(ei);

    // join: gather needs g_xw
    cudaStreamWaitEvent(0, s_evJoin, 0);
    k_gather_ln<<<(N_NODES + 7) / 8, 256>>>(x, b, gamma, beta, out);
}